// round 9
// baseline (speedup 1.0000x reference)
#include <cuda_runtime.h>
#include <stdint.h>

// Problem constants
constexpr int Fdim = 64;
constexpr int Rdim = 1024;
constexpr int Pdim = 128;
constexpr int BM   = 128;           // batch rows per CTA
constexpr int NCR  = 128;           // rules per chunk
constexpr int NCH  = Rdim / NCR;    // 8 chunks
constexpr int K8   = 33;            // k8 tiles (K padded to 264)
constexpr int QK8  = 3;             // k8 tiles per step
constexpr int NQ   = 11;            // steps per chunk
constexpr int NSTEP = NCH * NQ;     // 88
constexpr int NTH  = 256;           // 8 warps
constexpr int NT   = 8;             // n8-tiles per warp (64 rules), wc 2-way
constexpr int NBUF = 3;             // triple-buffered B
constexpr int STEP_FLOATS = 2 * QK8 * 4 * 32 * 4;   // 3072
constexpr int STEP_BYTES  = STEP_FLOATS * 4;        // 12288

#define LOG2E 1.4426950408889634f

// ---- Device-global scratch ----
__device__ uint32_t g_Bf[NSTEP * STEP_FLOATS];  // B in mma-fragment order, tf32
__device__ float4   g_kc[Rdim];                 // -pp*sign*log2e
__device__ float4   g_cc[Rdim];                 //  pp*sign*th*log2e
__device__ float4   g_mm[Rdim];                 //  mask

__device__ __forceinline__ float ex2f(float x) {
    float y; asm("ex2.approx.f32 %0, %1;" : "=f"(y) : "f"(x)); return y;
}
__device__ __forceinline__ float rcpf(float x) {
    float y; asm("rcp.approx.f32 %0, %1;" : "=f"(y) : "f"(x)); return y;
}
__device__ __forceinline__ uint32_t to_tf32(float f) {
    uint32_t r; asm("cvt.rna.tf32.f32 %0, %1;" : "=r"(r) : "f"(f)); return r;
}

// A fragment slot (float index) for logical element (row, k).
__device__ __forceinline__ int afrag_idx(int row, int k) {
    int m = row >> 4, g = row & 7, hi = (row >> 3) & 1;
    int k8 = k >> 3, tig = k & 3, khi = (k >> 2) & 1;
    return ((m * K8 + k8) * 32 + g * 4 + tig) * 4 + (hi + 2 * khi);
}

__global__ void prep_kernel(const float* __restrict__ C,    // [R][257]
                            const float* __restrict__ pp,   // [R]
                            const float* __restrict__ th,   // [R][4]
                            const float* __restrict__ sg,   // [R][4]
                            const float* __restrict__ mk)   // [R][4]
{
    int t = blockIdx.x * blockDim.x + threadIdx.x;
    // B layout per step: [wc(2)][k8q(3)][p(4)][lane(32)][4 words]
    if (t < Rdim * K8) {
        int r  = t / K8;
        int k8 = t - r * K8;
        int chunk = r >> 7;          // /128
        int rl = r & 127;
        int wc = rl >> 6;            // 0..1
        int nt = (rl >> 3) & 7;      // 0..7
        int nn = rl & 7;             // = g (operand column within n8)
        int p  = nt >> 1;
        int e  = nt & 1;
        int q = k8 / QK8, k8q = k8 - q * QK8;
        size_t stepBase = (size_t)(chunk * NQ + q) * STEP_FLOATS;
        #pragma unroll
        for (int tig = 0; tig < 4; tig++) {
            int kk0 = k8 * 8 + tig;          // khi=0
            int kk1 = k8 * 8 + 4 + tig;      // khi=1
            uint32_t v0 = (kk0 < 257) ? to_tf32(C[r * 257 + kk0]) : 0u;
            uint32_t v1 = (kk1 < 257) ? to_tf32(C[r * 257 + kk1]) : 0u;
            size_t idx = stepBase +
                (size_t)((((wc * QK8 + k8q) * 4 + p) * 32 + nn * 4 + tig) * 4 + e * 2);
            *(uint2*)&g_Bf[idx] = make_uint2(v0, v1);
        }
    }
    if (t < Rdim) {
        float s = pp[t];
        float kc[4], cc[4], mm[4];
        #pragma unroll
        for (int l = 0; l < 4; l++) {
            float sgn = sg[t * 4 + l];
            float tt  = th[t * 4 + l];
            kc[l] = -s * sgn * LOG2E;
            cc[l] =  s * sgn * tt * LOG2E;
            mm[l] = mk[t * 4 + l];
        }
        g_kc[t] = make_float4(kc[0], kc[1], kc[2], kc[3]);
        g_cc[t] = make_float4(cc[0], cc[1], cc[2], cc[3]);
        g_mm[t] = make_float4(mm[0], mm[1], mm[2], mm[3]);
    }
}

// ---- Shared memory layout (bytes) ----
constexpr int SMA  = 0;                       // A frags: 135168 B
constexpr int SMB  = 135168;                  // B triple buffer: 3*12288 = 36864 B
constexpr int SMXA = 172032;                  // sXa: 64 x 132 f32 = 33792 B
constexpr int SMEM_BYTES = 205824;

__global__ __launch_bounds__(NTH, 1)
void anfis_kernel(const float* __restrict__ x,        // [B][64]
                  const float* __restrict__ aw,       // [64]
                  const int*   __restrict__ fidx,     // [R][4]
                  const int*   __restrict__ ipair,    // [P][2]
                  float*       __restrict__ out)      // [B]
{
    extern __shared__ char smem[];
    const int tid  = threadIdx.x;
    const int wid  = tid >> 5;
    const int lane = tid & 31;
    const int g    = lane >> 2;
    const int tig  = lane & 3;
    const int wr   = wid >> 1;   // 0..3 : row group (32 rows)
    const int wc   = wid & 1;    // 0..1 : rule group (64 rules)
    const int b0   = blockIdx.x * BM;

    uint32_t* sA  = (uint32_t*)smem;
    float*    sXa = (float*)(smem + SMXA);
    const uint32_t smu  = (uint32_t)__cvta_generic_to_shared(smem);
    const uint32_t smAu = smu + SMA;
    const uint32_t smBu = smu + SMB;

    // ---- Prologue: build A fragments (tf32) + sXa (f32) ----
    #pragma unroll
    for (int pass = 0; pass < 8; pass++) {
        int idx = tid + pass * NTH;     // 0..2047
        int b = idx >> 4;
        int q = idx & 15;
        int f = q * 4;
        float4 xv = *(const float4*)&x[(b0 + b) * Fdim + f];
        float4 av = __ldg((const float4*)aw + q);
        float xa[4] = {xv.x * av.x, xv.y * av.y, xv.z * av.z, xv.w * av.w};
        #pragma unroll
        for (int j = 0; j < 4; j++) {
            sA[afrag_idx(b, f + j)]      = to_tf32(xa[j]);
            sA[afrag_idx(b, 64 + f + j)] = to_tf32(xa[j] * xa[j]);
            sXa[(f + j) * 132 + b] = xa[j];
        }
    }
    __syncthreads();
    {
        int b  = tid & 127;
        int pg = tid >> 7;
        for (int pi = pg; pi < Pdim; pi += 2) {
            int2 pr = __ldg((const int2*)ipair + pi);
            float v = sXa[pr.x * 132 + b] * sXa[pr.y * 132 + b];
            sA[afrag_idx(b, 128 + pi)] = to_tf32(v);
        }
        if (pg == 0) {
            sA[afrag_idx(b, 256)] = to_tf32(1.0f);
            #pragma unroll
            for (int k = 257; k < 264; k++) sA[afrag_idx(b, k)] = 0u;
        }
    }
    __syncthreads();

    // ---- B streamer: one step = 12288 B, triple-buffered ----
    auto issue = [&](int step, int buf) {
        const char* src = (const char*)g_Bf + (size_t)step * STEP_BYTES;
        uint32_t dst = smBu + (uint32_t)buf * STEP_BYTES;
        #pragma unroll
        for (int i = 0; i < 3; i++) {
            asm volatile("cp.async.cg.shared.global [%0], [%1], 16;"
                         :: "r"(dst + (tid + i * NTH) * 16),
                            "l"(src + (tid + i * NTH) * 16) : "memory");
        }
        asm volatile("cp.async.commit_group;" ::: "memory");
    };

    float accY[4] = {0.f, 0.f, 0.f, 0.f};
    float accS[4] = {0.f, 0.f, 0.f, 0.f};

    // Ping-pong accumulator sets (roles bound at compile time; all indexing static).
    float dA[2][NT][4], dB[2][NT][4];

    // Epilogue slice for one compile-time nt of chunk rchunk, consuming dprev.
    auto epi_slice = [&](int rchunk, int nt, const float (&dprev)[2][NT][4]) {
        #pragma unroll
        for (int ccc = 0; ccc < 2; ccc++) {
            int r = rchunk * NCR + (wc * NT + nt) * 8 + tig * 2 + ccc;
            float4 kc = __ldg(&g_kc[r]);
            float4 cc = __ldg(&g_cc[r]);
            float4 mm = __ldg(&g_mm[r]);
            int4   id = __ldg((const int4*)fidx + r);
            const float* x0 = sXa + id.x * 132;
            const float* x1 = sXa + id.y * 132;
            const float* x2 = sXa + id.z * 132;
            const float* x3 = sXa + id.w * 132;
            #pragma unroll
            for (int mi = 0; mi < 2; mi++) {
                #pragma unroll
                for (int hi = 0; hi < 2; hi++) {
                    int row = wr * 32 + mi * 16 + hi * 8 + g;
                    float u0 = ex2f(fmaf(kc.x, x0[row], cc.x));
                    float u1 = ex2f(fmaf(kc.y, x1[row], cc.y));
                    float u2 = ex2f(fmaf(kc.z, x2[row], cc.z));
                    float u3 = ex2f(fmaf(kc.w, x3[row], cc.w));
                    float fac = fmaf(mm.x, u0, 1.0f) * fmaf(mm.y, u1, 1.0f)
                              * fmaf(mm.z, u2, 1.0f) * fmaf(mm.w, u3, 1.0f);
                    float f = rcpf(fac);
                    accS[mi * 2 + hi] += f;
                    accY[mi * 2 + hi] =
                        fmaf(f, dprev[mi][nt][hi * 2 + ccc], accY[mi * 2 + hi]);
                }
            }
        }
    };

    // One chunk: 11 fully-unrolled steps; MMA into dcur, and (if doEpi) one
    // epilogue slice of the previous chunk per step (compile-time nt = qq).
    auto run_chunk = [&](int chunk, float (&dcur)[2][NT][4],
                         const float (&dprev)[2][NT][4], bool doEpi) {
        #pragma unroll
        for (int mi = 0; mi < 2; mi++)
            #pragma unroll
            for (int nt = 0; nt < NT; nt++)
                #pragma unroll
                for (int rr = 0; rr < 4; rr++) dcur[mi][nt][rr] = 0.f;

        #pragma unroll
        for (int qq = 0; qq < NQ; qq++) {
            int step = chunk * NQ + qq;
            if (step + 1 < NSTEP) {
                asm volatile("cp.async.wait_group 1;" ::: "memory");
            } else {
                asm volatile("cp.async.wait_group 0;" ::: "memory");
            }
            __syncthreads();
            if (step + 2 < NSTEP) {
                int nb = step + 2 - ((step + 2) / NBUF) * NBUF;
                issue(step + 2, nb);
            }

            uint32_t bufb = smBu + (uint32_t)(step - (step / NBUF) * NBUF) * STEP_BYTES;

            #pragma unroll
            for (int k8q = 0; k8q < QK8; k8q++) {
                int k8 = qq * QK8 + k8q;    // compile-time
                uint32_t a[2][4];
                #pragma unroll
                for (int mi = 0; mi < 2; mi++) {
                    uint32_t aAddr = smAu +
                        (uint32_t)((((wr * 2 + mi) * K8 + k8) * 32 + lane) * 16);
                    asm("ld.shared.v4.b32 {%0,%1,%2,%3}, [%4];"
                        : "=r"(a[mi][0]), "=r"(a[mi][1]),
                          "=r"(a[mi][2]), "=r"(a[mi][3]) : "r"(aAddr));
                }
                uint32_t bfr[NT][2];
                #pragma unroll
                for (int p = 0; p < NT / 2; p++) {
                    uint32_t bAddr = bufb +
                        (uint32_t)((((wc * QK8 + k8q) * 4 + p) * 32 + lane) * 16);
                    asm("ld.shared.v4.b32 {%0,%1,%2,%3}, [%4];"
                        : "=r"(bfr[2 * p][0]), "=r"(bfr[2 * p][1]),
                          "=r"(bfr[2 * p + 1][0]), "=r"(bfr[2 * p + 1][1])
                        : "r"(bAddr));
                }
                #pragma unroll
                for (int mi = 0; mi < 2; mi++)
                    #pragma unroll
                    for (int nt = 0; nt < NT; nt++) {
                        asm("mma.sync.aligned.m16n8k8.row.col.f32.tf32.tf32.f32 "
                            "{%0,%1,%2,%3}, {%4,%5,%6,%7}, {%8,%9}, {%0,%1,%2,%3};"
                            : "+f"(dcur[mi][nt][0]), "+f"(dcur[mi][nt][1]),
                              "+f"(dcur[mi][nt][2]), "+f"(dcur[mi][nt][3])
                            : "r"(a[mi][0]), "r"(a[mi][1]),
                              "r"(a[mi][2]), "r"(a[mi][3]),
                              "r"(bfr[nt][0]), "r"(bfr[nt][1]));
                    }
            }

            if (doEpi && qq < NT) epi_slice(chunk - 1, qq, dprev);
        }
    };

    issue(0, 0);
    issue(1, 1);

    for (int cp = 0; cp < NCH; cp += 2) {
        run_chunk(cp,     dA, dB, cp > 0);
        run_chunk(cp + 1, dB, dA, true);
    }
    // Tail: epilogue of the final chunk (in dB).
    #pragma unroll
    for (int nt = 0; nt < NT; nt++) epi_slice(NCH - 1, nt, dB);

    // ---- Reduce: shuffle over tig (4 lanes), then smem over wc (2 warps) ----
    #pragma unroll
    for (int s = 1; s <= 2; s <<= 1) {
        #pragma unroll
        for (int i = 0; i < 4; i++) {
            accY[i] += __shfl_xor_sync(0xffffffff, accY[i], s);
            accS[i] += __shfl_xor_sync(0xffffffff, accS[i], s);
        }
    }
    __syncthreads();
    float* redY = (float*)(smem + SMB);        // [128][2]
    float* redS = redY + 256;
    if (tig == 0) {
        #pragma unroll
        for (int i = 0; i < 4; i++) {
            int row = wr * 32 + (i >> 1) * 16 + (i & 1) * 8 + g;
            redY[row * 2 + wc] = accY[i];
            redS[row * 2 + wc] = accS[i];
        }
    }
    __syncthreads();
    if (tid < BM) {
        float sy = redY[tid * 2] + redY[tid * 2 + 1];
        float ss = redS[tid * 2] + redS[tid * 2 + 1];
        out[b0 + tid] = sy / (ss + 1e-8f);
    }
}

extern "C" void kernel_launch(void* const* d_in, const int* in_sizes, int n_in,
                              void* d_out, int out_size)
{
    const float* x    = (const float*)d_in[0];   // [16384,64]
    const float* aw   = (const float*)d_in[1];   // [64]
    const float* pp   = (const float*)d_in[2];   // [1024]
    const float* th   = (const float*)d_in[3];   // [1024,4]
    const float* sg   = (const float*)d_in[4];   // [1024,4]
    const float* mk   = (const float*)d_in[5];   // [1024,4]
    const float* C    = (const float*)d_in[6];   // [1024,257]
    const int*   fid  = (const int*)  d_in[7];   // [1024,4]
    const int*   ip   = (const int*)  d_in[8];   // [128,2]
    float* out = (float*)d_out;

    cudaFuncSetAttribute(anfis_kernel,
                         cudaFuncAttributeMaxDynamicSharedMemorySize,
                         SMEM_BYTES);

    prep_kernel<<<132, 256>>>(C, pp, th, sg, mk);
    anfis_kernel<<<16384 / BM, NTH, SMEM_BYTES>>>(x, aw, fid, ip, out);
}

// round 10
// speedup vs baseline: 2.0888x; 2.0888x over previous
#include <cuda_runtime.h>
#include <stdint.h>

// Problem constants
constexpr int Fdim = 64;
constexpr int Rdim = 1024;
constexpr int Pdim = 128;
constexpr int BM   = 64;            // batch rows per CTA (2 CTAs / SM)
constexpr int NCR  = 128;           // rules per chunk
constexpr int NCH  = Rdim / NCR;    // 8 chunks
constexpr int K8   = 33;            // k8 tiles (K padded to 264)
constexpr int QK8  = 3;             // k8 tiles per step
constexpr int NQ   = 11;            // steps per chunk
constexpr int NSTEP = NCH * NQ;     // 88
constexpr int NTH  = 128;           // 4 warps per CTA
constexpr int NT   = 16;            // n8-tiles per warp (whole 128-rule chunk)
constexpr int STEP_FLOATS = QK8 * 8 * 32 * 4;   // 3072
constexpr int STEP_BYTES  = STEP_FLOATS * 4;    // 12288

#define LOG2E 1.4426950408889634f

// ---- Device-global scratch ----
__device__ uint32_t g_Bf[NSTEP * STEP_FLOATS];  // B in mma-fragment order, tf32
__device__ float4   g_kc[Rdim];                 // -pp*sign*log2e
__device__ float4   g_cc[Rdim];                 //  pp*sign*th*log2e
__device__ float4   g_mm[Rdim];                 //  mask

__device__ __forceinline__ float ex2f(float x) {
    float y; asm("ex2.approx.f32 %0, %1;" : "=f"(y) : "f"(x)); return y;
}
__device__ __forceinline__ float rcpf(float x) {
    float y; asm("rcp.approx.f32 %0, %1;" : "=f"(y) : "f"(x)); return y;
}
__device__ __forceinline__ uint32_t to_tf32(float f) {
    uint32_t r; asm("cvt.rna.tf32.f32 %0, %1;" : "=r"(r) : "f"(f)); return r;
}

// A fragment slot (float index) for logical element (row 0..63, k).
__device__ __forceinline__ int afrag_idx(int row, int k) {
    int m = row >> 4, g = row & 7, hi = (row >> 3) & 1;
    int k8 = k >> 3, tig = k & 3, khi = (k >> 2) & 1;
    return ((m * K8 + k8) * 32 + g * 4 + tig) * 4 + (hi + 2 * khi);
}

__global__ void prep_kernel(const float* __restrict__ C,    // [R][257]
                            const float* __restrict__ pp,   // [R]
                            const float* __restrict__ th,   // [R][4]
                            const float* __restrict__ sg,   // [R][4]
                            const float* __restrict__ mk)   // [R][4]
{
    int t = blockIdx.x * blockDim.x + threadIdx.x;
    // B layout per step: [k8q(3)][p(8)][lane(32)][4 words]
    //   lane = nn*4+tig ; words = {nt=2p,khi0},{2p,khi1},{2p+1,khi0},{2p+1,khi1}
    if (t < Rdim * K8) {
        int r  = t / K8;
        int k8 = t - r * K8;
        int chunk = r >> 7;          // /128
        int rl = r & 127;
        int nt = rl >> 3;            // 0..15
        int nn = rl & 7;             // B operand column within n8
        int p  = nt >> 1;
        int e  = nt & 1;
        int q = k8 / QK8, k8q = k8 - q * QK8;
        size_t stepBase = (size_t)(chunk * NQ + q) * STEP_FLOATS;
        #pragma unroll
        for (int tig = 0; tig < 4; tig++) {
            int kk0 = k8 * 8 + tig;          // khi=0
            int kk1 = k8 * 8 + 4 + tig;      // khi=1
            uint32_t v0 = (kk0 < 257) ? to_tf32(C[r * 257 + kk0]) : 0u;
            uint32_t v1 = (kk1 < 257) ? to_tf32(C[r * 257 + kk1]) : 0u;
            size_t idx = stepBase +
                (size_t)(((k8q * 8 + p) * 32 + nn * 4 + tig) * 4 + e * 2);
            *(uint2*)&g_Bf[idx] = make_uint2(v0, v1);
        }
    }
    if (t < Rdim) {
        float s = pp[t];
        float kc[4], cc[4], mm[4];
        #pragma unroll
        for (int l = 0; l < 4; l++) {
            float sgn = sg[t * 4 + l];
            float tt  = th[t * 4 + l];
            kc[l] = -s * sgn * LOG2E;
            cc[l] =  s * sgn * tt * LOG2E;
            mm[l] = mk[t * 4 + l];
        }
        g_kc[t] = make_float4(kc[0], kc[1], kc[2], kc[3]);
        g_cc[t] = make_float4(cc[0], cc[1], cc[2], cc[3]);
        g_mm[t] = make_float4(mm[0], mm[1], mm[2], mm[3]);
    }
}

// ---- Shared memory layout (bytes) per CTA ----
constexpr int SMA  = 0;                       // A frags: 4*33*32*16 = 67584 B
constexpr int SMB  = 67584;                   // B double buffer: 2*12288 = 24576 B
constexpr int SMXA = 92160;                   // sXa: 64 x 68 f32 = 17408 B
constexpr int SMEM_BYTES = 109568;            // x2 CTAs = 219136 <= 228 KB/SM

__global__ __launch_bounds__(NTH, 2)
void anfis_kernel(const float* __restrict__ x,        // [B][64]
                  const float* __restrict__ aw,       // [64]
                  const int*   __restrict__ fidx,     // [R][4]
                  const int*   __restrict__ ipair,    // [P][2]
                  float*       __restrict__ out)      // [B]
{
    extern __shared__ char smem[];
    const int tid  = threadIdx.x;
    const int wid  = tid >> 5;   // 0..3 : one m16 tile per warp
    const int lane = tid & 31;
    const int g    = lane >> 2;
    const int tig  = lane & 3;
    const int b0   = blockIdx.x * BM;

    uint32_t* sA  = (uint32_t*)smem;
    float*    sXa = (float*)(smem + SMXA);
    const uint32_t smu  = (uint32_t)__cvta_generic_to_shared(smem);
    const uint32_t smAu = smu + SMA;
    const uint32_t smBu = smu + SMB;

    // ---- Prologue: build A fragments (tf32) + sXa (f32) ----
    #pragma unroll
    for (int pass = 0; pass < 8; pass++) {
        int idx = tid + pass * NTH;     // 0..1023
        int b = idx >> 4;               // 0..63
        int q = idx & 15;
        int f = q * 4;
        float4 xv = *(const float4*)&x[(b0 + b) * Fdim + f];
        float4 av = __ldg((const float4*)aw + q);
        float xa[4] = {xv.x * av.x, xv.y * av.y, xv.z * av.z, xv.w * av.w};
        #pragma unroll
        for (int j = 0; j < 4; j++) {
            sA[afrag_idx(b, f + j)]      = to_tf32(xa[j]);
            sA[afrag_idx(b, 64 + f + j)] = to_tf32(xa[j] * xa[j]);
            sXa[(f + j) * 68 + b] = xa[j];
        }
    }
    __syncthreads();
    {
        int b  = tid & 63;
        int pg = tid >> 6;              // 0..1
        for (int pi = pg; pi < Pdim; pi += 2) {
            int2 pr = __ldg((const int2*)ipair + pi);
            float v = sXa[pr.x * 68 + b] * sXa[pr.y * 68 + b];
            sA[afrag_idx(b, 128 + pi)] = to_tf32(v);
        }
        if (pg == 0) {
            sA[afrag_idx(b, 256)] = to_tf32(1.0f);
            #pragma unroll
            for (int k = 257; k < 264; k++) sA[afrag_idx(b, k)] = 0u;
        }
    }
    __syncthreads();

    // ---- B streamer: one step = 12288 B, double-buffered ----
    auto issue = [&](int step) {
        const char* src = (const char*)g_Bf + (size_t)step * STEP_BYTES;
        uint32_t dst = smBu + (uint32_t)(step & 1) * STEP_BYTES;
        #pragma unroll
        for (int i = 0; i < 6; i++) {
            asm volatile("cp.async.cg.shared.global [%0], [%1], 16;"
                         :: "r"(dst + (tid + i * NTH) * 16),
                            "l"(src + (tid + i * NTH) * 16) : "memory");
        }
        asm volatile("cp.async.commit_group;" ::: "memory");
    };

    float accY[2] = {0.f, 0.f};
    float accS[2] = {0.f, 0.f};

    issue(0);

    for (int chunk = 0; chunk < NCH; chunk++) {
        float d[NT][4];
        #pragma unroll
        for (int nt = 0; nt < NT; nt++)
            #pragma unroll
            for (int rr = 0; rr < 4; rr++) d[nt][rr] = 0.f;

        for (int qq = 0; qq < NQ; qq++) {
            int step = chunk * NQ + qq;
            asm volatile("cp.async.wait_group 0;" ::: "memory");
            __syncthreads();
            if (step + 1 < NSTEP) issue(step + 1);

            uint32_t bufb = smBu + (uint32_t)(step & 1) * STEP_BYTES;

            #pragma unroll
            for (int k8q = 0; k8q < QK8; k8q++) {
                int k8 = qq * QK8 + k8q;
                uint32_t a[4];
                {
                    uint32_t aAddr = smAu +
                        (uint32_t)(((wid * K8 + k8) * 32 + lane) * 16);
                    asm("ld.shared.v4.b32 {%0,%1,%2,%3}, [%4];"
                        : "=r"(a[0]), "=r"(a[1]), "=r"(a[2]), "=r"(a[3])
                        : "r"(aAddr));
                }
                uint32_t bfr[NT][2];
                #pragma unroll
                for (int p = 0; p < NT / 2; p++) {
                    uint32_t bAddr = bufb +
                        (uint32_t)(((k8q * 8 + p) * 32 + lane) * 16);
                    asm("ld.shared.v4.b32 {%0,%1,%2,%3}, [%4];"
                        : "=r"(bfr[2 * p][0]), "=r"(bfr[2 * p][1]),
                          "=r"(bfr[2 * p + 1][0]), "=r"(bfr[2 * p + 1][1])
                        : "r"(bAddr));
                }
                #pragma unroll
                for (int nt = 0; nt < NT; nt++) {
                    asm("mma.sync.aligned.m16n8k8.row.col.f32.tf32.tf32.f32 "
                        "{%0,%1,%2,%3}, {%4,%5,%6,%7}, {%8,%9}, {%0,%1,%2,%3};"
                        : "+f"(d[nt][0]), "+f"(d[nt][1]),
                          "+f"(d[nt][2]), "+f"(d[nt][3])
                        : "r"(a[0]), "r"(a[1]), "r"(a[2]), "r"(a[3]),
                          "r"(bfr[nt][0]), "r"(bfr[nt][1]));
                }
            }
        }

        // ---- Fused epilogue: firing = 1 / prod(1 + m*exp(-z)) ----
        #pragma unroll
        for (int nt = 0; nt < NT; nt++) {
            #pragma unroll
            for (int ccc = 0; ccc < 2; ccc++) {
                int r = chunk * NCR + nt * 8 + tig * 2 + ccc;
                float4 kc = __ldg(&g_kc[r]);
                float4 cc = __ldg(&g_cc[r]);
                float4 mm = __ldg(&g_mm[r]);
                int4   id = __ldg((const int4*)fidx + r);
                const float* x0 = sXa + id.x * 68;
                const float* x1 = sXa + id.y * 68;
                const float* x2 = sXa + id.z * 68;
                const float* x3 = sXa + id.w * 68;
                #pragma unroll
                for (int hi = 0; hi < 2; hi++) {
                    int row = wid * 16 + hi * 8 + g;
                    float u0 = ex2f(fmaf(kc.x, x0[row], cc.x));
                    float u1 = ex2f(fmaf(kc.y, x1[row], cc.y));
                    float u2 = ex2f(fmaf(kc.z, x2[row], cc.z));
                    float u3 = ex2f(fmaf(kc.w, x3[row], cc.w));
                    float fac = fmaf(mm.x, u0, 1.0f) * fmaf(mm.y, u1, 1.0f)
                              * fmaf(mm.z, u2, 1.0f) * fmaf(mm.w, u3, 1.0f);
                    float f = rcpf(fac);
                    accS[hi] += f;
                    accY[hi] = fmaf(f, d[nt][hi * 2 + ccc], accY[hi]);
                }
            }
        }
    }

    // ---- Reduce over tig (4 lanes) via shuffle; tig==0 stores directly ----
    #pragma unroll
    for (int s = 1; s <= 2; s <<= 1) {
        #pragma unroll
        for (int i = 0; i < 2; i++) {
            accY[i] += __shfl_xor_sync(0xffffffff, accY[i], s);
            accS[i] += __shfl_xor_sync(0xffffffff, accS[i], s);
        }
    }
    if (tig == 0) {
        #pragma unroll
        for (int hi = 0; hi < 2; hi++) {
            int row = wid * 16 + hi * 8 + g;
            out[b0 + row] = accY[hi] / (accS[hi] + 1e-8f);
        }
    }
}

extern "C" void kernel_launch(void* const* d_in, const int* in_sizes, int n_in,
                              void* d_out, int out_size)
{
    const float* x    = (const float*)d_in[0];   // [16384,64]
    const float* aw   = (const float*)d_in[1];   // [64]
    const float* pp   = (const float*)d_in[2];   // [1024]
    const float* th   = (const float*)d_in[3];   // [1024,4]
    const float* sg   = (const float*)d_in[4];   // [1024,4]
    const float* mk   = (const float*)d_in[5];   // [1024,4]
    const float* C    = (const float*)d_in[6];   // [1024,257]
    const int*   fid  = (const int*)  d_in[7];   // [1024,4]
    const int*   ip   = (const int*)  d_in[8];   // [128,2]
    float* out = (float*)d_out;

    cudaFuncSetAttribute(anfis_kernel,
                         cudaFuncAttributeMaxDynamicSharedMemorySize,
                         SMEM_BYTES);

    prep_kernel<<<132, 256>>>(C, pp, th, sg, mk);
    anfis_kernel<<<16384 / BM, NTH, SMEM_BYTES>>>(x, aw, fid, ip, out);
}

// round 11
// speedup vs baseline: 3.0341x; 1.4526x over previous
#include <cuda_runtime.h>
#include <cuda_fp16.h>
#include <stdint.h>
#include <string.h>

// Problem constants
constexpr int Fdim = 64;
constexpr int Rdim = 1024;
constexpr int Pdim = 128;
constexpr int BM   = 128;           // batch rows per CTA
constexpr int NCR  = 256;           // rules per chunk
constexpr int NCH  = Rdim / NCR;    // 4 chunks
constexpr int K16T = 18;            // k16 tiles (K padded to 288)
constexpr int QK   = 3;             // k16 tiles per step
constexpr int NQ   = 6;             // steps per chunk
constexpr int NSTEP = NCH * NQ;     // 24
constexpr int NTH  = 256;           // 8 warps
constexpr int NT   = 16;            // n8-tiles per warp (128 rules), wc 2-way
constexpr int STEP_WORDS = 2 * QK * 8 * 32 * 4;   // 6144 u32
constexpr int STEP_BYTES = STEP_WORDS * 4;        // 24576

#define LOG2E 1.4426950408889634f

// ---- Device-global scratch ----
__device__ uint32_t g_Bf[NSTEP * STEP_WORDS];   // B in m16n8k16 fragment order, fp16x2
__device__ float4   g_kc[Rdim];                 // -pp*sign*log2e
__device__ float4   g_cc[Rdim];                 //  pp*sign*th*log2e
__device__ float4   g_mm[Rdim];                 //  mask

__device__ __forceinline__ float ex2f(float x) {
    float y; asm("ex2.approx.f32 %0, %1;" : "=f"(y) : "f"(x)); return y;
}
__device__ __forceinline__ float rcpf(float x) {
    float y; asm("rcp.approx.f32 %0, %1;" : "=f"(y) : "f"(x)); return y;
}
__device__ __forceinline__ uint32_t packh(float lo, float hi) {
    __half2 h = __halves2half2(__float2half_rn(lo), __float2half_rn(hi));
    uint32_t u; memcpy(&u, &h, 4); return u;
}

// A fragment WORD index (u32) for (row, even k): word holds fp16 {k, k+1}.
//   m16n8k16 A frag: reg = hi + 2*khalf; lane = g*4 + tig
//   klo=k&15, khalf=klo>>3, tig=(klo&7)>>1
__device__ __forceinline__ int afrag_word(int row, int k) {
    int m = row >> 4, g = row & 7, hi = (row >> 3) & 1;
    int k16 = k >> 4, klo = k & 15;
    int khalf = klo >> 3, tig = (klo & 7) >> 1;
    return ((m * K16T + k16) * 32 + g * 4 + tig) * 4 + (hi + 2 * khalf);
}

__global__ void prep_kernel(const float* __restrict__ C,    // [R][257]
                            const float* __restrict__ pp,   // [R]
                            const float* __restrict__ th,   // [R][4]
                            const float* __restrict__ sg,   // [R][4]
                            const float* __restrict__ mk)   // [R][4]
{
    int t = blockIdx.x * blockDim.x + threadIdx.x;
    // B layout per step: [wc(2)][k16q(3)][p(8)][lane(32)][4 words]
    //   words = {nt=2p b0},{2p b1},{2p+1 b0},{2p+1 b1}
    //   b0 = fp16{C[r][k16*16+2tig], [+1]}, b1 = fp16{[+8+2tig], [+8+2tig+1]}
    if (t < Rdim * K16T) {
        int r   = t / K16T;
        int k16 = t - r * K16T;
        int chunk = r >> 8, rl = r & 255;
        int wc = rl >> 7;            // 0..1
        int nt = (rl >> 3) & 15;     // 0..15
        int nn = rl & 7;             // = g (operand column within n8)
        int p  = nt >> 1;
        int e  = nt & 1;
        int q = k16 / QK, k16q = k16 - q * QK;
        size_t stepBase = (size_t)(chunk * NQ + q) * STEP_WORDS;
        #pragma unroll
        for (int tig = 0; tig < 4; tig++) {
            int ka = k16 * 16 + 2 * tig;        // b0: ka, ka+1
            int kb = ka + 8;                    // b1: kb, kb+1
            float a0 = (ka     < 257) ? C[r * 257 + ka]     : 0.0f;
            float a1 = (ka + 1 < 257) ? C[r * 257 + ka + 1] : 0.0f;
            float b0 = (kb     < 257) ? C[r * 257 + kb]     : 0.0f;
            float b1 = (kb + 1 < 257) ? C[r * 257 + kb + 1] : 0.0f;
            size_t idx = stepBase +
                (size_t)((((wc * QK + k16q) * 8 + p) * 32 + nn * 4 + tig) * 4 + e * 2);
            *(uint2*)&g_Bf[idx] = make_uint2(packh(a0, a1), packh(b0, b1));
        }
    }
    if (t < Rdim) {
        float s = pp[t];
        float kc[4], cc[4], mm[4];
        #pragma unroll
        for (int l = 0; l < 4; l++) {
            float sgn = sg[t * 4 + l];
            float tt  = th[t * 4 + l];
            kc[l] = -s * sgn * LOG2E;
            cc[l] =  s * sgn * tt * LOG2E;
            mm[l] = mk[t * 4 + l];
        }
        g_kc[t] = make_float4(kc[0], kc[1], kc[2], kc[3]);
        g_cc[t] = make_float4(cc[0], cc[1], cc[2], cc[3]);
        g_mm[t] = make_float4(mm[0], mm[1], mm[2], mm[3]);
    }
}

// ---- Shared memory layout (bytes) ----
constexpr int SMA  = 0;                       // A frags: 8*18*32*16 = 73728? no:
// A: [m(8)][k16(18)][lane(32)][4 words] -> 8*18*32*16 = 73728 B? m = BM/16 = 8
constexpr int SMA_BYTES = (BM / 16) * K16T * 32 * 16;   // 73728
constexpr int SMB  = SMA_BYTES;               // B double buffer: 2*24576 = 49152 B
constexpr int SMXA = SMB + 2 * STEP_BYTES;    // sXa: 64 x 132 f32 = 33792 B
constexpr int SMEM_BYTES = SMXA + 64 * 132 * 4;   // 156672

__global__ __launch_bounds__(NTH, 1)
void anfis_kernel(const float* __restrict__ x,        // [B][64]
                  const float* __restrict__ aw,       // [64]
                  const int*   __restrict__ fidx,     // [R][4]
                  const int*   __restrict__ ipair,    // [P][2]
                  float*       __restrict__ out)      // [B]
{
    extern __shared__ char smem[];
    const int tid  = threadIdx.x;
    const int wid  = tid >> 5;
    const int lane = tid & 31;
    const int g    = lane >> 2;
    const int tig  = lane & 3;
    const int wr   = wid >> 1;   // 0..3 : row group (32 rows)
    const int wc   = wid & 1;    // 0..1 : rule group (128 rules)
    const int b0   = blockIdx.x * BM;

    uint32_t* sA  = (uint32_t*)smem;
    float*    sXa = (float*)(smem + SMXA);
    const uint32_t smu  = (uint32_t)__cvta_generic_to_shared(smem);
    const uint32_t smAu = smu + SMA;
    const uint32_t smBu = smu + SMB;

    // ---- Zero A region (covers k=257..287 padding) ----
    for (int i = tid; i < SMA_BYTES / 16; i += NTH)
        *(uint4*)(smem + i * 16) = make_uint4(0, 0, 0, 0);
    __syncthreads();

    // ---- Prologue: build A fragments (fp16) + sXa (f32) ----
    #pragma unroll
    for (int pass = 0; pass < 8; pass++) {
        int idx = tid + pass * NTH;     // 0..2047
        int b = idx >> 4;               // 0..127
        int q = idx & 15;
        int f = q * 4;
        float4 xv = *(const float4*)&x[(b0 + b) * Fdim + f];
        float4 av = __ldg((const float4*)aw + q);
        float xa[4] = {xv.x * av.x, xv.y * av.y, xv.z * av.z, xv.w * av.w};
        // k = f..f+3: words at (tig, tig+1), same reg
        sA[afrag_word(b, f)]          = packh(xa[0], xa[1]);
        sA[afrag_word(b, f + 2)]      = packh(xa[2], xa[3]);
        sA[afrag_word(b, 64 + f)]     = packh(xa[0] * xa[0], xa[1] * xa[1]);
        sA[afrag_word(b, 64 + f + 2)] = packh(xa[2] * xa[2], xa[3] * xa[3]);
        sXa[(f + 0) * 132 + b] = xa[0];
        sXa[(f + 1) * 132 + b] = xa[1];
        sXa[(f + 2) * 132 + b] = xa[2];
        sXa[(f + 3) * 132 + b] = xa[3];
    }
    __syncthreads();
    {
        int b  = tid & 127;
        int pg = tid >> 7;              // 0..1
        // interactions: pairs (pi, pi+1) -> one fp16x2 word
        for (int pp2 = pg; pp2 < Pdim / 2; pp2 += 2) {
            int pi = pp2 * 2;
            int2 pr0 = __ldg((const int2*)ipair + pi);
            int2 pr1 = __ldg((const int2*)ipair + pi + 1);
            float v0 = sXa[pr0.x * 132 + b] * sXa[pr0.y * 132 + b];
            float v1 = sXa[pr1.x * 132 + b] * sXa[pr1.y * 132 + b];
            sA[afrag_word(b, 128 + pi)] = packh(v0, v1);
        }
        if (pg == 0)
            sA[afrag_word(b, 256)] = packh(1.0f, 0.0f);   // ones; k=257 pad = 0
    }
    __syncthreads();

    // ---- B streamer (all threads): one step = 24576 B ----
    auto issue = [&](int step) {
        const char* src = (const char*)g_Bf + (size_t)step * STEP_BYTES;
        uint32_t dst = smBu + (uint32_t)(step & 1) * STEP_BYTES;
        #pragma unroll
        for (int i = 0; i < 6; i++) {
            asm volatile("cp.async.cg.shared.global [%0], [%1], 16;"
                         :: "r"(dst + (tid + i * NTH) * 16),
                            "l"(src + (tid + i * NTH) * 16) : "memory");
        }
        asm volatile("cp.async.commit_group;" ::: "memory");
    };

    float accY[4] = {0.f, 0.f, 0.f, 0.f};
    float accS[4] = {0.f, 0.f, 0.f, 0.f};

    issue(0);

    for (int chunk = 0; chunk < NCH; chunk++) {
        float d[2][NT][4];
        #pragma unroll
        for (int mi = 0; mi < 2; mi++)
            #pragma unroll
            for (int nt = 0; nt < NT; nt++)
                #pragma unroll
                for (int rr = 0; rr < 4; rr++) d[mi][nt][rr] = 0.f;

        for (int qq = 0; qq < NQ; qq++) {
            int step = chunk * NQ + qq;
            asm volatile("cp.async.wait_group 0;" ::: "memory");
            __syncthreads();
            if (step + 1 < NSTEP) issue(step + 1);

            uint32_t bufb = smBu + (uint32_t)(step & 1) * STEP_BYTES;

            #pragma unroll
            for (int kq = 0; kq < QK; kq++) {
                int k16 = qq * QK + kq;
                uint32_t a[2][4];
                #pragma unroll
                for (int mi = 0; mi < 2; mi++) {
                    uint32_t aAddr = smAu +
                        (uint32_t)((((wr * 2 + mi) * K16T + k16) * 32 + lane) * 16);
                    asm("ld.shared.v4.b32 {%0,%1,%2,%3}, [%4];"
                        : "=r"(a[mi][0]), "=r"(a[mi][1]),
                          "=r"(a[mi][2]), "=r"(a[mi][3]) : "r"(aAddr));
                }
                uint32_t bfr[NT][2];
                #pragma unroll
                for (int p = 0; p < NT / 2; p++) {
                    uint32_t bAddr = bufb +
                        (uint32_t)((((wc * QK + kq) * 8 + p) * 32 + lane) * 16);
                    asm("ld.shared.v4.b32 {%0,%1,%2,%3}, [%4];"
                        : "=r"(bfr[2 * p][0]), "=r"(bfr[2 * p][1]),
                          "=r"(bfr[2 * p + 1][0]), "=r"(bfr[2 * p + 1][1])
                        : "r"(bAddr));
                }
                #pragma unroll
                for (int mi = 0; mi < 2; mi++)
                    #pragma unroll
                    for (int nt = 0; nt < NT; nt++) {
                        asm("mma.sync.aligned.m16n8k16.row.col.f32.f16.f16.f32 "
                            "{%0,%1,%2,%3}, {%4,%5,%6,%7}, {%8,%9}, {%0,%1,%2,%3};"
                            : "+f"(d[mi][nt][0]), "+f"(d[mi][nt][1]),
                              "+f"(d[mi][nt][2]), "+f"(d[mi][nt][3])
                            : "r"(a[mi][0]), "r"(a[mi][1]),
                              "r"(a[mi][2]), "r"(a[mi][3]),
                              "r"(bfr[nt][0]), "r"(bfr[nt][1]));
                    }
            }
        }

        // ---- Fused epilogue: firing = 1 / prod(1 + m*exp(-z)) ----
        #pragma unroll
        for (int nt = 0; nt < NT; nt++) {
            #pragma unroll
            for (int ccc = 0; ccc < 2; ccc++) {
                int r = chunk * NCR + (wc * NT + nt) * 8 + tig * 2 + ccc;
                float4 kc = __ldg(&g_kc[r]);
                float4 cc = __ldg(&g_cc[r]);
                float4 mm = __ldg(&g_mm[r]);
                int4   id = __ldg((const int4*)fidx + r);
                const float* x0 = sXa + id.x * 132;
                const float* x1 = sXa + id.y * 132;
                const float* x2 = sXa + id.z * 132;
                const float* x3 = sXa + id.w * 132;
                #pragma unroll
                for (int mi = 0; mi < 2; mi++) {
                    #pragma unroll
                    for (int hi = 0; hi < 2; hi++) {
                        int row = wr * 32 + mi * 16 + hi * 8 + g;
                        float u0 = ex2f(fmaf(kc.x, x0[row], cc.x));
                        float u1 = ex2f(fmaf(kc.y, x1[row], cc.y));
                        float u2 = ex2f(fmaf(kc.z, x2[row], cc.z));
                        float u3 = ex2f(fmaf(kc.w, x3[row], cc.w));
                        float fac = fmaf(mm.x, u0, 1.0f) * fmaf(mm.y, u1, 1.0f)
                                  * fmaf(mm.z, u2, 1.0f) * fmaf(mm.w, u3, 1.0f);
                        float f = rcpf(fac);
                        accS[mi * 2 + hi] += f;
                        accY[mi * 2 + hi] =
                            fmaf(f, d[mi][nt][hi * 2 + ccc], accY[mi * 2 + hi]);
                    }
                }
            }
        }
    }

    // ---- Reduce: shuffle over tig (4 lanes), then smem over wc (2 warps) ----
    #pragma unroll
    for (int s = 1; s <= 2; s <<= 1) {
        #pragma unroll
        for (int i = 0; i < 4; i++) {
            accY[i] += __shfl_xor_sync(0xffffffff, accY[i], s);
            accS[i] += __shfl_xor_sync(0xffffffff, accS[i], s);
        }
    }
    __syncthreads();
    float* redY = (float*)(smem + SMB);        // [128][2]
    float* redS = redY + 256;
    if (tig == 0) {
        #pragma unroll
        for (int i = 0; i < 4; i++) {
            int row = wr * 32 + (i >> 1) * 16 + (i & 1) * 8 + g;
            redY[row * 2 + wc] = accY[i];
            redS[row * 2 + wc] = accS[i];
        }
    }
    __syncthreads();
    if (tid < BM) {
        float sy = redY[tid * 2] + redY[tid * 2 + 1];
        float ss = redS[tid * 2] + redS[tid * 2 + 1];
        out[b0 + tid] = sy / (ss + 1e-8f);
    }
}

extern "C" void kernel_launch(void* const* d_in, const int* in_sizes, int n_in,
                              void* d_out, int out_size)
{
    const float* x    = (const float*)d_in[0];   // [16384,64]
    const float* aw   = (const float*)d_in[1];   // [64]
    const float* pp   = (const float*)d_in[2];   // [1024]
    const float* th   = (const float*)d_in[3];   // [1024,4]
    const float* sg   = (const float*)d_in[4];   // [1024,4]
    const float* mk   = (const float*)d_in[5];   // [1024,4]
    const float* C    = (const float*)d_in[6];   // [1024,257]
    const int*   fid  = (const int*)  d_in[7];   // [1024,4]
    const int*   ip   = (const int*)  d_in[8];   // [128,2]
    float* out = (float*)d_out;

    cudaFuncSetAttribute(anfis_kernel,
                         cudaFuncAttributeMaxDynamicSharedMemorySize,
                         SMEM_BYTES);

    prep_kernel<<<144, 256>>>(C, pp, th, sg, mk);
    anfis_kernel<<<16384 / BM, NTH, SMEM_BYTES>>>(x, aw, fid, ip, out);
}

// round 17
// speedup vs baseline: 3.1719x; 1.0454x over previous
#include <cuda_runtime.h>
#include <cuda_fp16.h>
#include <stdint.h>
#include <string.h>

// Problem constants (R11 config, QK/NQ retuned: 12 bigger steps)
constexpr int Fdim = 64;
constexpr int Rdim = 1024;
constexpr int Pdim = 128;
constexpr int BM   = 128;           // batch rows per CTA
constexpr int NCR  = 256;           // rules per chunk
constexpr int NCH  = Rdim / NCR;    // 4 chunks
constexpr int K16T = 18;            // k16 tiles (K padded to 288)
constexpr int QK   = 6;             // k16 tiles per step  (was 3)
constexpr int NQ   = 3;             // steps per chunk     (was 6)
constexpr int NSTEP = NCH * NQ;     // 12
constexpr int NTH  = 256;           // 8 warps
constexpr int NT   = 16;            // n8-tiles per warp (128 rules), wc 2-way
constexpr int STEP_WORDS = 2 * QK * 8 * 32 * 4;   // 12288 u32
constexpr int STEP_BYTES = STEP_WORDS * 4;        // 49152

#define LOG2E 1.4426950408889634f

// ---- Device-global scratch ----
__device__ uint32_t g_Bf[NSTEP * STEP_WORDS];   // B in m16n8k16 fragment order, fp16x2
__device__ float4   g_kc[Rdim];                 // -pp*sign*log2e
__device__ float4   g_cc[Rdim];                 //  pp*sign*th*log2e
__device__ float4   g_mm[Rdim];                 //  mask

__device__ __forceinline__ float ex2f(float x) {
    float y; asm("ex2.approx.f32 %0, %1;" : "=f"(y) : "f"(x)); return y;
}
__device__ __forceinline__ float rcpf(float x) {
    float y; asm("rcp.approx.f32 %0, %1;" : "=f"(y) : "f"(x)); return y;
}
__device__ __forceinline__ uint32_t packh(float lo, float hi) {
    __half2 h = __halves2half2(__float2half_rn(lo), __float2half_rn(hi));
    uint32_t u; memcpy(&u, &h, 4); return u;
}

// A fragment WORD index (u32) for (row, even k): word holds fp16 {k, k+1}.
__device__ __forceinline__ int afrag_word(int row, int k) {
    int m = row >> 4, g = row & 7, hi = (row >> 3) & 1;
    int k16 = k >> 4, klo = k & 15;
    int khalf = klo >> 3, tig = (klo & 7) >> 1;
    return ((m * K16T + k16) * 32 + g * 4 + tig) * 4 + (hi + 2 * khalf);
}

__global__ void prep_kernel(const float* __restrict__ C,    // [R][257]
                            const float* __restrict__ pp,   // [R]
                            const float* __restrict__ th,   // [R][4]
                            const float* __restrict__ sg,   // [R][4]
                            const float* __restrict__ mk)   // [R][4]
{
    int t = blockIdx.x * blockDim.x + threadIdx.x;
    // B layout per step: [wc(2)][k16q(QK)][p(8)][lane(32)][4 words]  (R11 formula)
    if (t < Rdim * K16T) {
        int r   = t / K16T;
        int k16 = t - r * K16T;
        int chunk = r >> 8, rl = r & 255;
        int wc = rl >> 7;            // 0..1
        int nt = (rl >> 3) & 15;     // 0..15
        int nn = rl & 7;             // = g (operand column within n8)
        int p  = nt >> 1;
        int e  = nt & 1;
        int q = k16 / QK, k16q = k16 - q * QK;
        size_t stepBase = (size_t)(chunk * NQ + q) * STEP_WORDS;
        #pragma unroll
        for (int tig = 0; tig < 4; tig++) {
            int ka = k16 * 16 + 2 * tig;        // b0: ka, ka+1
            int kb = ka + 8;                    // b1: kb, kb+1
            float a0 = (ka     < 257) ? C[r * 257 + ka]     : 0.0f;
            float a1 = (ka + 1 < 257) ? C[r * 257 + ka + 1] : 0.0f;
            float b0 = (kb     < 257) ? C[r * 257 + kb]     : 0.0f;
            float b1 = (kb + 1 < 257) ? C[r * 257 + kb + 1] : 0.0f;
            size_t idx = stepBase +
                (size_t)((((wc * QK + k16q) * 8 + p) * 32 + nn * 4 + tig) * 4 + e * 2);
            *(uint2*)&g_Bf[idx] = make_uint2(packh(a0, a1), packh(b0, b1));
        }
    }
    if (t < Rdim) {
        float s = pp[t];
        float kc[4], cc[4], mm[4];
        #pragma unroll
        for (int l = 0; l < 4; l++) {
            float sgn = sg[t * 4 + l];
            float tt  = th[t * 4 + l];
            kc[l] = -s * sgn * LOG2E;
            cc[l] =  s * sgn * tt * LOG2E;
            mm[l] = mk[t * 4 + l];
        }
        g_kc[t] = make_float4(kc[0], kc[1], kc[2], kc[3]);
        g_cc[t] = make_float4(cc[0], cc[1], cc[2], cc[3]);
        g_mm[t] = make_float4(mm[0], mm[1], mm[2], mm[3]);
    }
}

// ---- Shared memory layout (bytes) ----
constexpr int SMA_BYTES = (BM / 16) * K16T * 32 * 16;   // 73728
constexpr int SMB  = SMA_BYTES;               // B double buffer: 2*49152 = 98304
constexpr int SMXA = SMB + 2 * STEP_BYTES;    // sXa: 64 x 132 f32 = 33792
constexpr int SMEM_BYTES = SMXA + 64 * 132 * 4;   // 205824

__global__ __launch_bounds__(NTH, 1)
void anfis_kernel(const float* __restrict__ x,        // [B][64]
                  const float* __restrict__ aw,       // [64]
                  const int*   __restrict__ fidx,     // [R][4]
                  const int*   __restrict__ ipair,    // [P][2]
                  float*       __restrict__ out)      // [B]
{
    extern __shared__ char smem[];
    const int tid  = threadIdx.x;
    const int wid  = tid >> 5;
    const int lane = tid & 31;
    const int g    = lane >> 2;
    const int tig  = lane & 3;
    const int wr   = wid >> 1;   // 0..3 : row group (32 rows)
    const int wc   = wid & 1;    // 0..1 : rule group (128 rules)
    const int b0   = blockIdx.x * BM;

    uint32_t* sA   = (uint32_t*)smem;
    float*    sXa  = (float*)(smem + SMXA);
    const uint32_t smu  = (uint32_t)__cvta_generic_to_shared(smem);
    const uint32_t smAu = smu;
    const uint32_t smBu = smu + SMB;

    // ---- Zero A region (full, covers all k padding) ----
    for (int i = tid; i < SMA_BYTES / 16; i += NTH)
        *(uint4*)(smem + i * 16) = make_uint4(0, 0, 0, 0);
    __syncthreads();

    // ---- Prologue: build A fragments (fp16) + sXa (f32) ----
    #pragma unroll
    for (int pass = 0; pass < 8; pass++) {
        int idx = tid + pass * NTH;     // 0..2047
        int b = idx >> 4;               // 0..127
        int q = idx & 15;
        int f = q * 4;
        float4 xv = *(const float4*)&x[(b0 + b) * Fdim + f];
        float4 av = __ldg((const float4*)aw + q);
        float xa[4] = {xv.x * av.x, xv.y * av.y, xv.z * av.z, xv.w * av.w};
        sA[afrag_word(b, f)]          = packh(xa[0], xa[1]);
        sA[afrag_word(b, f + 2)]      = packh(xa[2], xa[3]);
        sA[afrag_word(b, 64 + f)]     = packh(xa[0] * xa[0], xa[1] * xa[1]);
        sA[afrag_word(b, 64 + f + 2)] = packh(xa[2] * xa[2], xa[3] * xa[3]);
        sXa[(f + 0) * 132 + b] = xa[0];
        sXa[(f + 1) * 132 + b] = xa[1];
        sXa[(f + 2) * 132 + b] = xa[2];
        sXa[(f + 3) * 132 + b] = xa[3];
    }
    __syncthreads();
    {
        int b  = tid & 127;
        int pg = tid >> 7;              // 0..1
        for (int pp2 = pg; pp2 < Pdim / 2; pp2 += 2) {
            int pi = pp2 * 2;
            int2 pr0 = __ldg((const int2*)ipair + pi);
            int2 pr1 = __ldg((const int2*)ipair + pi + 1);
            float v0 = sXa[pr0.x * 132 + b] * sXa[pr0.y * 132 + b];
            float v1 = sXa[pr1.x * 132 + b] * sXa[pr1.y * 132 + b];
            sA[afrag_word(b, 128 + pi)] = packh(v0, v1);
        }
        if (pg == 0)
            sA[afrag_word(b, 256)] = packh(1.0f, 0.0f);
    }
    __syncthreads();

    // ---- B streamer (all threads): one step = 49152 B, double-buffered ----
    auto issue = [&](int step) {
        const char* src = (const char*)g_Bf + (size_t)step * STEP_BYTES;
        uint32_t dst = smBu + (uint32_t)(step & 1) * STEP_BYTES;
        #pragma unroll
        for (int i = 0; i < 12; i++) {
            asm volatile("cp.async.cg.shared.global [%0], [%1], 16;"
                         :: "r"(dst + (tid + i * NTH) * 16),
                            "l"(src + (tid + i * NTH) * 16) : "memory");
        }
        asm volatile("cp.async.commit_group;" ::: "memory");
    };

    float accY[4] = {0.f, 0.f, 0.f, 0.f};
    float accS[4] = {0.f, 0.f, 0.f, 0.f};

    issue(0);

    for (int chunk = 0; chunk < NCH; chunk++) {
        float d[2][NT][4];
        #pragma unroll
        for (int mi = 0; mi < 2; mi++)
            #pragma unroll
            for (int nt = 0; nt < NT; nt++)
                #pragma unroll
                for (int rr = 0; rr < 4; rr++) d[mi][nt][rr] = 0.f;

        for (int qq = 0; qq < NQ; qq++) {
            int step = chunk * NQ + qq;
            asm volatile("cp.async.wait_group 0;" ::: "memory");
            __syncthreads();
            if (step + 1 < NSTEP) issue(step + 1);

            uint32_t bufb = smBu + (uint32_t)(step & 1) * STEP_BYTES;

            #pragma unroll
            for (int kq = 0; kq < QK; kq++) {
                int k16 = qq * QK + kq;
                uint32_t a[2][4];
                #pragma unroll
                for (int mi = 0; mi < 2; mi++) {
                    uint32_t aAddr = smAu +
                        (uint32_t)((((wr * 2 + mi) * K16T + k16) * 32 + lane) * 16);
                    asm("ld.shared.v4.b32 {%0,%1,%2,%3}, [%4];"
                        : "=r"(a[mi][0]), "=r"(a[mi][1]),
                          "=r"(a[mi][2]), "=r"(a[mi][3]) : "r"(aAddr));
                }
                uint32_t bfr[NT][2];
                #pragma unroll
                for (int p = 0; p < NT / 2; p++) {
                    uint32_t bAddr = bufb +
                        (uint32_t)((((wc * QK + kq) * 8 + p) * 32 + lane) * 16);
                    asm("ld.shared.v4.b32 {%0,%1,%2,%3}, [%4];"
                        : "=r"(bfr[2 * p][0]), "=r"(bfr[2 * p][1]),
                          "=r"(bfr[2 * p + 1][0]), "=r"(bfr[2 * p + 1][1])
                        : "r"(bAddr));
                }
                #pragma unroll
                for (int mi = 0; mi < 2; mi++)
                    #pragma unroll
                    for (int nt = 0; nt < NT; nt++) {
                        asm("mma.sync.aligned.m16n8k16.row.col.f32.f16.f16.f32 "
                            "{%0,%1,%2,%3}, {%4,%5,%6,%7}, {%8,%9}, {%0,%1,%2,%3};"
                            : "+f"(d[mi][nt][0]), "+f"(d[mi][nt][1]),
                              "+f"(d[mi][nt][2]), "+f"(d[mi][nt][3])
                            : "r"(a[mi][0]), "r"(a[mi][1]),
                              "r"(a[mi][2]), "r"(a[mi][3]),
                              "r"(bfr[nt][0]), "r"(bfr[nt][1]));
                    }
            }
        }

        // ---- Fused epilogue: firing = 1 / prod(1 + m*exp(-z))  (R11 verbatim) ----
        #pragma unroll
        for (int nt = 0; nt < NT; nt++) {
            #pragma unroll
            for (int ccc = 0; ccc < 2; ccc++) {
                int r = chunk * NCR + (wc * NT + nt) * 8 + tig * 2 + ccc;
                float4 kc = __ldg(&g_kc[r]);
                float4 cc = __ldg(&g_cc[r]);
                float4 mm = __ldg(&g_mm[r]);
                int4   id = __ldg((const int4*)fidx + r);
                const float* x0 = sXa + id.x * 132;
                const float* x1 = sXa + id.y * 132;
                const float* x2 = sXa + id.z * 132;
                const float* x3 = sXa + id.w * 132;
                #pragma unroll
                for (int mi = 0; mi < 2; mi++) {
                    #pragma unroll
                    for (int hi = 0; hi < 2; hi++) {
                        int row = wr * 32 + mi * 16 + hi * 8 + g;
                        float u0 = ex2f(fmaf(kc.x, x0[row], cc.x));
                        float u1 = ex2f(fmaf(kc.y, x1[row], cc.y));
                        float u2 = ex2f(fmaf(kc.z, x2[row], cc.z));
                        float u3 = ex2f(fmaf(kc.w, x3[row], cc.w));
                        float fac = fmaf(mm.x, u0, 1.0f) * fmaf(mm.y, u1, 1.0f)
                                  * fmaf(mm.z, u2, 1.0f) * fmaf(mm.w, u3, 1.0f);
                        float f = rcpf(fac);
                        accS[mi * 2 + hi] += f;
                        accY[mi * 2 + hi] =
                            fmaf(f, d[mi][nt][hi * 2 + ccc], accY[mi * 2 + hi]);
                    }
                }
            }
        }
    }

    // ---- Reduce: shuffle over tig (4 lanes), then smem over wc (2 warps) ----
    #pragma unroll
    for (int s = 1; s <= 2; s <<= 1) {
        #pragma unroll
        for (int i = 0; i < 4; i++) {
            accY[i] += __shfl_xor_sync(0xffffffff, accY[i], s);
            accS[i] += __shfl_xor_sync(0xffffffff, accS[i], s);
        }
    }
    __syncthreads();
    float* redY = (float*)(smem + SMB);
    float* redS = redY + 256;
    if (tig == 0) {
        #pragma unroll
        for (int i = 0; i < 4; i++) {
            int row = wr * 32 + (i >> 1) * 16 + (i & 1) * 8 + g;
            redY[row * 2 + wc] = accY[i];
            redS[row * 2 + wc] = accS[i];
        }
    }
    __syncthreads();
    if (tid < BM) {
        float sy = redY[tid * 2] + redY[tid * 2 + 1];
        float ss = redS[tid * 2] + redS[tid * 2 + 1];
        out[b0 + tid] = sy / (ss + 1e-8f);
    }
}

extern "C" void kernel_launch(void* const* d_in, const int* in_sizes, int n_in,
                              void* d_out, int out_size)
{
    const float* x    = (const float*)d_in[0];   // [16384,64]
    const float* aw   = (const float*)d_in[1];   // [64]
    const float* pp   = (const float*)d_in[2];   // [1024]
    const float* th   = (const float*)d_in[3];   // [1024,4]
    const float* sg   = (const float*)d_in[4];   // [1024,4]
    const float* mk   = (const float*)d_in[5];   // [1024,4]
    const float* C    = (const float*)d_in[6];   // [1024,257]
    const int*   fid  = (const int*)  d_in[7];   // [1024,4]
    const int*   ip   = (const int*)  d_in[8];   // [128,2]
    float* out = (float*)d_out;

    cudaFuncSetAttribute(anfis_kernel,
                         cudaFuncAttributeMaxDynamicSharedMemorySize,
                         SMEM_BYTES);

    prep_kernel<<<144, 256>>>(C, pp, th, sg, mk);
    anfis_kernel<<<16384 / BM, NTH, SMEM_BYTES>>>(x, aw, fid, ip, out);
}